// round 16
// baseline (speedup 1.0000x reference)
#include <cuda_runtime.h>
#include <cuda_fp16.h>
#include <math.h>

// Problem constants (fixed by setup_inputs)
#define B_    2
#define Q_    12240
#define E_    256
#define H_    8
#define L_    4
#define KP_   4
#define HD_   32
#define VLEN_ 12240
#define BQ_   (B_ * Q_)      // 24480
#define BV_   (B_ * VLEN_)   // 24480

// Scratch (static __device__ — no allocation)
__device__ __half2 g_vproj_h[(size_t)BV_ * 128];   // (B, Vlen, 128 half2)
__device__ int4    g_sinfo[(size_t)BQ_ * 128];     // per-sample {base, dxdy, wx, wy}
__device__ float   g_attnw[(size_t)BQ_ * 128];     // (bq, h,l,k)
__device__ float   g_acc[(size_t)BQ_ * E_];        // sampled output

// ---------------------------------------------------------------------------
// FP16 tensor-core GEMM, double-buffered smem, one sync per k-iter.
// F1X (compile-time): true -> single hi*hi pass (for fp16-stored outputs);
//                     false -> 3x split (lo*hi + hi*lo + hi*hi), fp32-class.
// EPI 0: final projection (A, B0) -> fp32 C0, grid.x=2
// EPI 1: value*Wv -> fp16 vproj (C0), grid.x=2
// EPI 5: queries front, grid.x=3: bx<2 -> Woff/sinfo; bx==2 -> Wattn/softmax
// ---------------------------------------------------------------------------
__device__ __forceinline__ void mma_f16(float* c, const unsigned* a, const unsigned* b) {
    asm volatile(
        "mma.sync.aligned.m16n8k16.row.col.f32.f16.f16.f32 "
        "{%0,%1,%2,%3}, {%4,%5,%6,%7}, {%8,%9}, {%0,%1,%2,%3};\n"
        : "+f"(c[0]), "+f"(c[1]), "+f"(c[2]), "+f"(c[3])
        : "r"(a[0]), "r"(a[1]), "r"(a[2]), "r"(a[3]), "r"(b[0]), "r"(b[1]));
}

__device__ __forceinline__ void split_h2(float x, float y, __half2& hi, __half2& lo) {
    __half hx = __float2half_rn(x), hy = __float2half_rn(y);
    hi = __halves2half2(hx, hy);
    lo = __halves2half2(__float2half_rn(x - __half2float(hx)),
                        __float2half_rn(y - __half2float(hy)));
}

#define GBM 128
#define GBK 32
#define A_LDH 20      // half2 leading dim for A  (16 + 4 pad)
#define B_LDH 136     // half2 leading dim for B  (128 + 8 pad)
#define AS_SZ (GBM * A_LDH)             // 2560 half2
#define BS_SZ (16 * B_LDH)              // 2176 half2
#define STG_H2 (2 * AS_SZ + 2 * BS_SZ)  // 9472 half2 = 37888 B
#define SMEM_TOT (2 * STG_H2 * 4)       // 75776 B

template<int EPI, bool F1X>
__global__ __launch_bounds__(256, 2)
void gemm_f16(const float* __restrict__ A,
              const float* __restrict__ B0, const float* __restrict__ B1,
              void* __restrict__ C0, void* __restrict__ C1,
              int M, int K,
              const float* __restrict__ ref, const float* __restrict__ boff,
              const float* __restrict__ battn) {
    extern __shared__ __half2 dsm[];

    const int tid  = threadIdx.x;
    const int warp = tid >> 5;
    const int lane = tid & 31;
    const int grp  = lane >> 2;
    const int tg   = lane & 3;
    const int m_off = (warp >> 2) * 64;
    const int n_off = (warp & 3) * 32;
    const int bm = blockIdx.y * GBM;
    const int bx = blockIdx.x;

    // operand routing (compile-time shaped)
    const float* Bp; int Nb, bn;
    if (EPI == 5) {
        if (bx < 2) { Bp = B0; Nb = 256; bn = bx * 128; }
        else        { Bp = B1; Nb = 128; bn = 0; }
    } else { Bp = B0; Nb = 256; bn = bx * 128; }

    float cc[4][4][4];
#pragma unroll
    for (int i = 0; i < 4; i++)
#pragma unroll
        for (int j = 0; j < 4; j++)
#pragma unroll
            for (int r = 0; r < 4; r++) cc[i][j][r] = 0.f;

    // per-thread staging addresses
    int ar[4], akq[4];
#pragma unroll
    for (int i = 0; i < 4; i++) {
        int f4 = tid + i * 256;
        ar[i]  = f4 >> 3;
        akq[i] = (f4 & 7) << 2;
    }
    int bk2[2], bn4[2];
#pragma unroll
    for (int i = 0; i < 2; i++) {
        int u = tid + i * 256;
        bk2[i] = u >> 5;
        bn4[i] = (u & 31) << 2;
    }

    float4 pa[4], pb[4];
#pragma unroll
    for (int i = 0; i < 4; i++) {
        pa[i] = make_float4(0.f, 0.f, 0.f, 0.f);
        if (bm + ar[i] < M)
            pa[i] = *(const float4*)&A[(size_t)(bm + ar[i]) * K + akq[i]];
    }
#pragma unroll
    for (int i = 0; i < 2; i++) {
        const float* p0 = &Bp[(size_t)(2 * bk2[i]) * Nb + bn + bn4[i]];
        pb[2 * i]     = *(const float4*)p0;
        pb[2 * i + 1] = *(const float4*)(p0 + Nb);
    }

    // store stage 0
    {
        __half2* As_hi = dsm;
        __half2* As_lo = As_hi + AS_SZ;
        __half2* Bs_hi = As_lo + AS_SZ;
        __half2* Bs_lo = Bs_hi + BS_SZ;
#pragma unroll
        for (int i = 0; i < 4; i++) {
            __half2 h0, l0, h1, l1;
            split_h2(pa[i].x, pa[i].y, h0, l0);
            split_h2(pa[i].z, pa[i].w, h1, l1);
            int o = ar[i] * A_LDH + (akq[i] >> 1);
            As_hi[o] = h0; As_hi[o + 1] = h1;
            if (!F1X) { As_lo[o] = l0; As_lo[o + 1] = l1; }
        }
#pragma unroll
        for (int i = 0; i < 2; i++) {
            float4 v0 = pb[2 * i], v1 = pb[2 * i + 1];
            __half2 h0, l0, h1, l1, h2v, l2v, h3, l3;
            split_h2(v0.x, v1.x, h0, l0);
            split_h2(v0.y, v1.y, h1, l1);
            split_h2(v0.z, v1.z, h2v, l2v);
            split_h2(v0.w, v1.w, h3, l3);
            int o = bk2[i] * B_LDH + bn4[i];
            Bs_hi[o] = h0; Bs_hi[o+1] = h1; Bs_hi[o+2] = h2v; Bs_hi[o+3] = h3;
            if (!F1X) { Bs_lo[o] = l0; Bs_lo[o+1] = l1; Bs_lo[o+2] = l2v; Bs_lo[o+3] = l3; }
        }
    }
    __syncthreads();

    int buf = 0;
    for (int k0 = 0; k0 < K; k0 += GBK) {
        const bool notlast = (k0 + GBK < K);
        if (notlast) {
            const int kn = k0 + GBK;
#pragma unroll
            for (int i = 0; i < 4; i++) {
                pa[i] = make_float4(0.f, 0.f, 0.f, 0.f);
                if (bm + ar[i] < M)
                    pa[i] = *(const float4*)&A[(size_t)(bm + ar[i]) * K + kn + akq[i]];
            }
#pragma unroll
            for (int i = 0; i < 2; i++) {
                const float* p0 = &Bp[(size_t)(kn + 2 * bk2[i]) * Nb + bn + bn4[i]];
                pb[2 * i]     = *(const float4*)p0;
                pb[2 * i + 1] = *(const float4*)(p0 + Nb);
            }
        }

        // ---- mma on current buffer ----
        {
            const __half2* As_hi = dsm + buf * STG_H2;
            const __half2* As_lo = As_hi + AS_SZ;
            const __half2* Bs_hi = As_lo + AS_SZ;
            const __half2* Bs_lo = Bs_hi + BS_SZ;
#pragma unroll
            for (int ch = 0; ch < 2; ch++) {
                const int ko2 = ch * 8;
                unsigned bh[4][2], bl[4][2];
#pragma unroll
                for (int an = 0; an < 4; an++) {
                    int c0 = n_off + an * 8 + grp;
                    bh[an][0] = *(const unsigned*)&Bs_hi[(ko2 + tg) * B_LDH + c0];
                    bh[an][1] = *(const unsigned*)&Bs_hi[(ko2 + tg + 4) * B_LDH + c0];
                    if (!F1X) {
                        bl[an][0] = *(const unsigned*)&Bs_lo[(ko2 + tg) * B_LDH + c0];
                        bl[an][1] = *(const unsigned*)&Bs_lo[(ko2 + tg + 4) * B_LDH + c0];
                    }
                }
#pragma unroll
                for (int am = 0; am < 4; am++) {
                    int r0 = m_off + am * 16 + grp;
                    unsigned ah[4], al[4];
                    ah[0] = *(const unsigned*)&As_hi[r0 * A_LDH + ko2 + tg];
                    ah[1] = *(const unsigned*)&As_hi[(r0 + 8) * A_LDH + ko2 + tg];
                    ah[2] = *(const unsigned*)&As_hi[r0 * A_LDH + ko2 + tg + 4];
                    ah[3] = *(const unsigned*)&As_hi[(r0 + 8) * A_LDH + ko2 + tg + 4];
                    if (!F1X) {
                        al[0] = *(const unsigned*)&As_lo[r0 * A_LDH + ko2 + tg];
                        al[1] = *(const unsigned*)&As_lo[(r0 + 8) * A_LDH + ko2 + tg];
                        al[2] = *(const unsigned*)&As_lo[r0 * A_LDH + ko2 + tg + 4];
                        al[3] = *(const unsigned*)&As_lo[(r0 + 8) * A_LDH + ko2 + tg + 4];
                    }
#pragma unroll
                    for (int an = 0; an < 4; an++) {
                        if (!F1X) {
                            mma_f16(cc[am][an], al, bh[an]);
                            mma_f16(cc[am][an], ah, bl[an]);
                        }
                        mma_f16(cc[am][an], ah, bh[an]);
                    }
                }
            }
        }

        // ---- split+store next tile into other buffer, then single sync ----
        if (notlast) {
            __half2* As_hi = dsm + (buf ^ 1) * STG_H2;
            __half2* As_lo = As_hi + AS_SZ;
            __half2* Bs_hi = As_lo + AS_SZ;
            __half2* Bs_lo = Bs_hi + BS_SZ;
#pragma unroll
            for (int i = 0; i < 4; i++) {
                __half2 h0, l0, h1, l1;
                split_h2(pa[i].x, pa[i].y, h0, l0);
                split_h2(pa[i].z, pa[i].w, h1, l1);
                int o = ar[i] * A_LDH + (akq[i] >> 1);
                As_hi[o] = h0; As_hi[o + 1] = h1;
                if (!F1X) { As_lo[o] = l0; As_lo[o + 1] = l1; }
            }
#pragma unroll
            for (int i = 0; i < 2; i++) {
                float4 v0 = pb[2 * i], v1 = pb[2 * i + 1];
                __half2 h0, l0, h1, l1, h2v, l2v, h3, l3;
                split_h2(v0.x, v1.x, h0, l0);
                split_h2(v0.y, v1.y, h1, l1);
                split_h2(v0.z, v1.z, h2v, l2v);
                split_h2(v0.w, v1.w, h3, l3);
                int o = bk2[i] * B_LDH + bn4[i];
                Bs_hi[o] = h0; Bs_hi[o+1] = h1; Bs_hi[o+2] = h2v; Bs_hi[o+3] = h3;
                if (!F1X) { Bs_lo[o] = l0; Bs_lo[o+1] = l1; Bs_lo[o+2] = l2v; Bs_lo[o+3] = l3; }
            }
            __syncthreads();
        }
        buf ^= 1;
    }

    // ======================= epilogues =======================
    if (EPI == 0) {
        float* C = (float*)C0;
#pragma unroll
        for (int am = 0; am < 4; am++) {
            int r0 = bm + m_off + am * 16 + grp;
#pragma unroll
            for (int an = 0; an < 4; an++) {
                int c0 = bn + n_off + an * 8 + 2 * tg;
                if (r0 < M)
                    *(float2*)&C[(size_t)r0 * 256 + c0] = make_float2(cc[am][an][0], cc[am][an][1]);
                if (r0 + 8 < M)
                    *(float2*)&C[(size_t)(r0 + 8) * 256 + c0] = make_float2(cc[am][an][2], cc[am][an][3]);
            }
        }
    } else if (EPI == 1) {
        // fp16 store -> vproj (N=256, 128 half2 per row)
        __half2* C = (__half2*)C0;
#pragma unroll
        for (int am = 0; am < 4; am++) {
            int r0 = bm + m_off + am * 16 + grp;
#pragma unroll
            for (int an = 0; an < 4; an++) {
                int c0 = bn + n_off + an * 8 + 2 * tg;
                if (r0 < M)
                    C[(size_t)r0 * 128 + (c0 >> 1)] = __floats2half2_rn(cc[am][an][0], cc[am][an][1]);
                if (r0 + 8 < M)
                    C[(size_t)(r0 + 8) * 128 + (c0 >> 1)] = __floats2half2_rn(cc[am][an][2], cc[am][an][3]);
            }
        }
    } else if (EPI == 5 && bx < 2) {
        // sample-info epilogue
        int4* C = (int4*)C0;
#pragma unroll
        for (int am = 0; am < 4; am++) {
#pragma unroll
            for (int rh = 0; rh < 2; rh++) {
                int row = bm + m_off + am * 16 + grp + rh * 8;
                if (row >= M) continue;
#pragma unroll
                for (int an = 0; an < 4; an++) {
                    int c0 = bn + n_off + an * 8 + 2 * tg;   // even: x; c0+1: y
                    int l = (c0 >> 3) & 3;
                    const int Wl = 96 >> l;
                    const int start = 12288 - (12288 >> (2 * l));
                    const float scale = 0.5f * (float)(Wl - 1);
                    float rx = __ldg(&ref[(size_t)row * 8 + l * 2 + 0]);
                    float ry = __ldg(&ref[(size_t)row * 8 + l * 2 + 1]);
                    float o0 = tanhf(cc[am][an][rh * 2 + 0] + __ldg(&boff[c0]));
                    float o1 = tanhf(cc[am][an][rh * 2 + 1] + __ldg(&boff[c0 + 1]));
                    float lx = fminf(fmaxf(rx + o0, -1.f), 1.f);
                    float ly = fminf(fmaxf(ry + o1, -1.f), 1.f);
                    float x = (lx + 1.f) * scale;
                    float y = (ly + 1.f) * scale;
                    float x0f = floorf(x), y0f = floorf(y);
                    float wx = x - x0f, wy = y - y0f;
                    int x0 = min(max((int)x0f, 0), Wl - 1);
                    int x1 = min(x0 + 1, Wl - 1);
                    int y0 = min(max((int)y0f, 0), Wl - 1);
                    int y1 = min(y0 + 1, Wl - 1);
                    int base = (start + y0 * Wl + x0) * 128;
                    int dxdy = (((y1 - y0) * Wl * 128) << 8) | ((x1 - x0) * 128);
                    C[(size_t)row * 128 + (c0 >> 1)] =
                        make_int4(base, dxdy, __float_as_int(wx), __float_as_int(wy));
                }
            }
        }
    } else if (EPI == 5) {
        // softmax epilogue (N=128)
        float* C = (float*)C1;
#pragma unroll
        for (int am = 0; am < 4; am++) {
#pragma unroll
            for (int rh = 0; rh < 2; rh++) {
                int row = bm + m_off + am * 16 + grp + rh * 8;
#pragma unroll
                for (int hd2 = 0; hd2 < 2; hd2++) {
                    float v[4];
#pragma unroll
                    for (int q = 0; q < 4; q++) {
                        int an = hd2 * 2 + (q >> 1);
                        int s = q & 1;
                        int col = n_off + an * 8 + 2 * tg + s;
                        v[q] = cc[am][an][rh * 2 + s] + __ldg(&battn[col]);
                    }
                    float m = fmaxf(fmaxf(v[0], v[1]), fmaxf(v[2], v[3]));
                    m = fmaxf(m, __shfl_xor_sync(0xffffffffu, m, 1));
                    m = fmaxf(m, __shfl_xor_sync(0xffffffffu, m, 2));
                    float e[4], sum = 0.f;
#pragma unroll
                    for (int q = 0; q < 4; q++) { e[q] = __expf(v[q] - m); sum += e[q]; }
                    sum += __shfl_xor_sync(0xffffffffu, sum, 1);
                    sum += __shfl_xor_sync(0xffffffffu, sum, 2);
                    float inv = 1.f / sum;
                    if (row < M) {
#pragma unroll
                        for (int a2 = 0; a2 < 2; a2++) {
                            int an = hd2 * 2 + a2;
                            int c0 = n_off + an * 8 + 2 * tg;
                            *(float2*)&C[(size_t)row * 128 + c0] =
                                make_float2(e[a2 * 2] * inv, e[a2 * 2 + 1] * inv);
                        }
                    }
                }
            }
        }
    }
}

// ---------------------------------------------------------------------------
// Deformable sampling: warp = one (bq, head-quad). 8 lanes per head, each lane
// handles 4 channels via 8B (uint2 = 2x half2) gathers.
// ---------------------------------------------------------------------------
__device__ __forceinline__ float4 ld_corner(const __half2* p) {
    uint2 u = __ldg((const uint2*)p);
    float2 fa = __half22float2(*(__half2*)&u.x);
    float2 fb = __half22float2(*(__half2*)&u.y);
    return make_float4(fa.x, fa.y, fb.x, fb.y);
}

__global__ __launch_bounds__(256)
void sample_half(const __half2* __restrict__ vp,
                 const int4* __restrict__ sinfo,
                 const float* __restrict__ attnw,
                 float* __restrict__ acc) {
    const int gwarp = (blockIdx.x * blockDim.x + threadIdx.x) >> 5;
    const int lane = threadIdx.x & 31;
    if (gwarp >= BQ_ * 2) return;
    const int wp = gwarp & 1;
    const int bq = gwarp >> 1;
    const int b = bq / Q_;
    const int hs = lane >> 3;      // 0..3
    const int c4 = lane & 7;       // channel group (4 channels)
    const int h = wp * 4 + hs;

    const int4*  sp = sinfo + (size_t)bq * 128 + h * 16;
    const float* wq = attnw + (size_t)bq * 128 + h * 16;
    const __half2* vb = vp + (size_t)b * VLEN_ * 128 + h * 16 + c4 * 2;

    float a0 = 0.f, a1 = 0.f, a2 = 0.f, a3 = 0.f;
#pragma unroll
    for (int s = 0; s < 16; s++) {
        int4 si = __ldg(&sp[s]);
        float w = __ldg(&wq[s]);
        float wx = __int_as_float(si.z);
        float wy = __int_as_float(si.w);
        float wb = w * wy;
        float wa = w - wb;
        float w01 = wa * wx, w00 = wa - w01;
        float w11 = wb * wx, w10 = wb - w11;
        int dx = si.y & 255;
        int dy = si.y >> 8;
        const __half2* p = vb + si.x;
        float4 f00 = ld_corner(p);
        float4 f01 = ld_corner(p + dx);
        float4 f10 = ld_corner(p + dy);
        float4 f11 = ld_corner(p + dx + dy);
        a0 = fmaf(w00, f00.x, fmaf(w01, f01.x, fmaf(w10, f10.x, fmaf(w11, f11.x, a0))));
        a1 = fmaf(w00, f00.y, fmaf(w01, f01.y, fmaf(w10, f10.y, fmaf(w11, f11.y, a1))));
        a2 = fmaf(w00, f00.z, fmaf(w01, f01.z, fmaf(w10, f10.z, fmaf(w11, f11.z, a2))));
        a3 = fmaf(w00, f00.w, fmaf(w01, f01.w, fmaf(w10, f10.w, fmaf(w11, f11.w, a3))));
    }
    *(float4*)&acc[(size_t)bq * 256 + h * 32 + c4 * 4] = make_float4(a0, a1, a2, a3);
}

// ---------------------------------------------------------------------------
extern "C" void kernel_launch(void* const* d_in, const int* in_sizes, int n_in,
                              void* d_out, int out_size) {
    const float* queries = (const float*)d_in[0];
    const float* ref     = (const float*)d_in[1];
    const float* value   = (const float*)d_in[2];
    const float* Wv      = (const float*)d_in[3];
    const float* Woff    = (const float*)d_in[4];
    const float* boff    = (const float*)d_in[5];
    const float* Wattn   = (const float*)d_in[6];
    const float* battn   = (const float*)d_in[7];
    const float* Wout    = (const float*)d_in[8];
    float* out = (float*)d_out;

    __half2* vproj;
    int4* sinfo;
    float *attnw, *acc;
    cudaGetSymbolAddress((void**)&vproj, g_vproj_h);
    cudaGetSymbolAddress((void**)&sinfo, g_sinfo);
    cudaGetSymbolAddress((void**)&attnw, g_attnw);
    cudaGetSymbolAddress((void**)&acc,   g_acc);

    cudaFuncSetAttribute((const void*)gemm_f16<1, true>,  cudaFuncAttributeMaxDynamicSharedMemorySize, SMEM_TOT);
    cudaFuncSetAttribute((const void*)gemm_f16<5, false>, cudaFuncAttributeMaxDynamicSharedMemorySize, SMEM_TOT);
    cudaFuncSetAttribute((const void*)gemm_f16<0, false>, cudaFuncAttributeMaxDynamicSharedMemorySize, SMEM_TOT);

    const int mblk = (BQ_ + GBM - 1) / GBM;   // 192

    // 1) value projection -> fp16 vproj (1x fp16, compile-time specialized)
    gemm_f16<1, true><<<dim3(2, mblk), 256, SMEM_TOT>>>(
        value, Wv, nullptr, vproj, nullptr, BQ_, E_, nullptr, nullptr, nullptr);
    // 2) queries front: sinfo (bx<2) + attnw softmax (bx==2), 3x precision
    gemm_f16<5, false><<<dim3(3, mblk), 256, SMEM_TOT>>>(
        queries, Woff, Wattn, sinfo, attnw, BQ_, E_, ref, boff, battn);
    // 3) deformable bilinear sampling
    {
        int total_threads = BQ_ * 2 * 32;
        sample_half<<<(total_threads + 255) / 256, 256>>>(vproj, sinfo, attnw, acc);
    }
    // 4) output projection -> d_out (3x precision)
    gemm_f16<0, false><<<dim3(2, mblk), 256, SMEM_TOT>>>(
        acc, Wout, nullptr, out, nullptr, BQ_, E_, nullptr, nullptr, nullptr);
}

// round 17
// speedup vs baseline: 1.6866x; 1.6866x over previous
#include <cuda_runtime.h>
#include <cuda_fp16.h>
#include <math.h>

// Problem constants (fixed by setup_inputs)
#define B_    2
#define Q_    12240
#define E_    256
#define H_    8
#define L_    4
#define KP_   4
#define HD_   32
#define VLEN_ 12240
#define BQ_   (B_ * Q_)      // 24480
#define BV_   (B_ * VLEN_)   // 24480

// Scratch (static __device__ — no allocation)
__device__ __half2 g_vproj_h[(size_t)BV_ * 128];   // (B, Vlen, 128 half2)
__device__ int4    g_sinfo[(size_t)BQ_ * 128];     // per-sample {base, dxdy, wx, wy}
__device__ float   g_attnw[(size_t)BQ_ * 128];     // (bq, h,l,k)
__device__ float   g_acc[(size_t)BQ_ * E_];        // sampled output

// ---------------------------------------------------------------------------
// FP16 tensor-core GEMM, double-buffered smem, one sync per k-iter.
// Mainloop is a compile-time-specialized template device function:
//   F1X = true  -> single hi*hi pass (vproj blocks; output stored fp16 anyway)
//   F1X = false -> 3x split (lo*hi + hi*lo + hi*hi), fp32-class accuracy
// The F1X choice is ONE block-uniform branch at kernel top (never inside the
// unrolled loop — R15's mistake) and launches stay merged (R16's mistake).
// EPI 0: final projection (A=acc, B=Wout, fp32 out, N=256, grid.x=2)
// EPI 5: merged front-end, grid.x=5:
//        bx 0-1: A=value,   B=Wv    -> fp16 vproj    (1x mode)
//        bx 2-3: A=queries, B=Woff  -> sinfo         (3x mode)
//        bx 4  : A=queries, B=Wattn -> attnw softmax (3x mode)
// ---------------------------------------------------------------------------
__device__ __forceinline__ void mma_f16(float* c, const unsigned* a, const unsigned* b) {
    asm volatile(
        "mma.sync.aligned.m16n8k16.row.col.f32.f16.f16.f32 "
        "{%0,%1,%2,%3}, {%4,%5,%6,%7}, {%8,%9}, {%0,%1,%2,%3};\n"
        : "+f"(c[0]), "+f"(c[1]), "+f"(c[2]), "+f"(c[3])
        : "r"(a[0]), "r"(a[1]), "r"(a[2]), "r"(a[3]), "r"(b[0]), "r"(b[1]));
}

__device__ __forceinline__ void split_h2(float x, float y, __half2& hi, __half2& lo) {
    __half hx = __float2half_rn(x), hy = __float2half_rn(y);
    hi = __halves2half2(hx, hy);
    lo = __halves2half2(__float2half_rn(x - __half2float(hx)),
                        __float2half_rn(y - __half2float(hy)));
}

#define GBM 128
#define GBK 32
#define A_LDH 20      // half2 leading dim for A  (16 + 4 pad)
#define B_LDH 136     // half2 leading dim for B  (128 + 8 pad)
#define AS_SZ (GBM * A_LDH)             // 2560 half2
#define BS_SZ (16 * B_LDH)              // 2176 half2
#define STG_H2 (2 * AS_SZ + 2 * BS_SZ)  // 9472 half2 = 37888 B
#define SMEM_TOT (2 * STG_H2 * 4)       // 75776 B

template<bool F1X>
__device__ __forceinline__ void gemm_mainloop(
    const float* __restrict__ Ap, const float* __restrict__ Bp,
    int Nb, int bn, int bm, int M, int K,
    __half2* dsm, float cc[4][4][4],
    int tid, int grp, int tg, int m_off, int n_off) {

    // per-thread staging addresses
    int ar[4], akq[4];
#pragma unroll
    for (int i = 0; i < 4; i++) {
        int f4 = tid + i * 256;
        ar[i]  = f4 >> 3;
        akq[i] = (f4 & 7) << 2;
    }
    int bk2[2], bn4[2];
#pragma unroll
    for (int i = 0; i < 2; i++) {
        int u = tid + i * 256;
        bk2[i] = u >> 5;
        bn4[i] = (u & 31) << 2;
    }

    float4 pa[4], pb[4];
    // initial gmem loads (k0 = 0)
#pragma unroll
    for (int i = 0; i < 4; i++) {
        pa[i] = make_float4(0.f, 0.f, 0.f, 0.f);
        if (bm + ar[i] < M)
            pa[i] = *(const float4*)&Ap[(size_t)(bm + ar[i]) * K + akq[i]];
    }
#pragma unroll
    for (int i = 0; i < 2; i++) {
        const float* p0 = &Bp[(size_t)(2 * bk2[i]) * Nb + bn + bn4[i]];
        pb[2 * i]     = *(const float4*)p0;
        pb[2 * i + 1] = *(const float4*)(p0 + Nb);
    }

    // store stage 0
    {
        __half2* As_hi = dsm;
        __half2* As_lo = As_hi + AS_SZ;
        __half2* Bs_hi = As_lo + AS_SZ;
        __half2* Bs_lo = Bs_hi + BS_SZ;
#pragma unroll
        for (int i = 0; i < 4; i++) {
            __half2 h0, l0, h1, l1;
            split_h2(pa[i].x, pa[i].y, h0, l0);
            split_h2(pa[i].z, pa[i].w, h1, l1);
            int o = ar[i] * A_LDH + (akq[i] >> 1);
            As_hi[o] = h0; As_hi[o + 1] = h1;
            if (!F1X) { As_lo[o] = l0; As_lo[o + 1] = l1; }
        }
#pragma unroll
        for (int i = 0; i < 2; i++) {
            float4 v0 = pb[2 * i], v1 = pb[2 * i + 1];
            __half2 h0, l0, h1, l1, h2v, l2v, h3, l3;
            split_h2(v0.x, v1.x, h0, l0);
            split_h2(v0.y, v1.y, h1, l1);
            split_h2(v0.z, v1.z, h2v, l2v);
            split_h2(v0.w, v1.w, h3, l3);
            int o = bk2[i] * B_LDH + bn4[i];
            Bs_hi[o] = h0; Bs_hi[o+1] = h1; Bs_hi[o+2] = h2v; Bs_hi[o+3] = h3;
            if (!F1X) { Bs_lo[o] = l0; Bs_lo[o+1] = l1; Bs_lo[o+2] = l2v; Bs_lo[o+3] = l3; }
        }
    }
    __syncthreads();

    int buf = 0;
    for (int k0 = 0; k0 < K; k0 += GBK) {
        const bool notlast = (k0 + GBK < K);
        // ---- prefetch next tile ----
        if (notlast) {
            const int kn = k0 + GBK;
#pragma unroll
            for (int i = 0; i < 4; i++) {
                pa[i] = make_float4(0.f, 0.f, 0.f, 0.f);
                if (bm + ar[i] < M)
                    pa[i] = *(const float4*)&Ap[(size_t)(bm + ar[i]) * K + kn + akq[i]];
            }
#pragma unroll
            for (int i = 0; i < 2; i++) {
                const float* p0 = &Bp[(size_t)(kn + 2 * bk2[i]) * Nb + bn + bn4[i]];
                pb[2 * i]     = *(const float4*)p0;
                pb[2 * i + 1] = *(const float4*)(p0 + Nb);
            }
        }

        // ---- mma on current buffer ----
        {
            const __half2* As_hi = dsm + buf * STG_H2;
            const __half2* As_lo = As_hi + AS_SZ;
            const __half2* Bs_hi = As_lo + AS_SZ;
            const __half2* Bs_lo = Bs_hi + BS_SZ;
#pragma unroll
            for (int ch = 0; ch < 2; ch++) {
                const int ko2 = ch * 8;
                unsigned bh[4][2], bl[4][2];
#pragma unroll
                for (int an = 0; an < 4; an++) {
                    int c0 = n_off + an * 8 + grp;
                    bh[an][0] = *(const unsigned*)&Bs_hi[(ko2 + tg) * B_LDH + c0];
                    bh[an][1] = *(const unsigned*)&Bs_hi[(ko2 + tg + 4) * B_LDH + c0];
                    if (!F1X) {
                        bl[an][0] = *(const unsigned*)&Bs_lo[(ko2 + tg) * B_LDH + c0];
                        bl[an][1] = *(const unsigned*)&Bs_lo[(ko2 + tg + 4) * B_LDH + c0];
                    }
                }
#pragma unroll
                for (int am = 0; am < 4; am++) {
                    int r0 = m_off + am * 16 + grp;
                    unsigned ah[4], al[4];
                    ah[0] = *(const unsigned*)&As_hi[r0 * A_LDH + ko2 + tg];
                    ah[1] = *(const unsigned*)&As_hi[(r0 + 8) * A_LDH + ko2 + tg];
                    ah[2] = *(const unsigned*)&As_hi[r0 * A_LDH + ko2 + tg + 4];
                    ah[3] = *(const unsigned*)&As_hi[(r0 + 8) * A_LDH + ko2 + tg + 4];
                    if (!F1X) {
                        al[0] = *(const unsigned*)&As_lo[r0 * A_LDH + ko2 + tg];
                        al[1] = *(const unsigned*)&As_lo[(r0 + 8) * A_LDH + ko2 + tg];
                        al[2] = *(const unsigned*)&As_lo[r0 * A_LDH + ko2 + tg + 4];
                        al[3] = *(const unsigned*)&As_lo[(r0 + 8) * A_LDH + ko2 + tg + 4];
                    }
#pragma unroll
                    for (int an = 0; an < 4; an++) {
                        if (!F1X) {
                            mma_f16(cc[am][an], al, bh[an]);
                            mma_f16(cc[am][an], ah, bl[an]);
                        }
                        mma_f16(cc[am][an], ah, bh[an]);
                    }
                }
            }
        }

        // ---- split+store next tile into other buffer, then single sync ----
        if (notlast) {
            __half2* As_hi = dsm + (buf ^ 1) * STG_H2;
            __half2* As_lo = As_hi + AS_SZ;
            __half2* Bs_hi = As_lo + AS_SZ;
            __half2* Bs_lo = Bs_hi + BS_SZ;
#pragma unroll
            for (int i = 0; i < 4; i++) {
                __half2 h0, l0, h1, l1;
                split_h2(pa[i].x, pa[i].y, h0, l0);
                split_h2(pa[i].z, pa[i].w, h1, l1);
                int o = ar[i] * A_LDH + (akq[i] >> 1);
                As_hi[o] = h0; As_hi[o + 1] = h1;
                if (!F1X) { As_lo[o] = l0; As_lo[o + 1] = l1; }
            }
#pragma unroll
            for (int i = 0; i < 2; i++) {
                float4 v0 = pb[2 * i], v1 = pb[2 * i + 1];
                __half2 h0, l0, h1, l1, h2v, l2v, h3, l3;
                split_h2(v0.x, v1.x, h0, l0);
                split_h2(v0.y, v1.y, h1, l1);
                split_h2(v0.z, v1.z, h2v, l2v);
                split_h2(v0.w, v1.w, h3, l3);
                int o = bk2[i] * B_LDH + bn4[i];
                Bs_hi[o] = h0; Bs_hi[o+1] = h1; Bs_hi[o+2] = h2v; Bs_hi[o+3] = h3;
                if (!F1X) { Bs_lo[o] = l0; Bs_lo[o+1] = l1; Bs_lo[o+2] = l2v; Bs_lo[o+3] = l3; }
            }
            __syncthreads();
        }
        buf ^= 1;
    }
}

template<int EPI>
__global__ __launch_bounds__(256, 2)
void gemm_3xfp16(const float* __restrict__ A, const float* __restrict__ A2,
                 const float* __restrict__ B0, const float* __restrict__ B1,
                 const float* __restrict__ B2,
                 void* __restrict__ C0, void* __restrict__ C1, void* __restrict__ C2,
                 int M, int K,
                 const float* __restrict__ ref, const float* __restrict__ boff,
                 const float* __restrict__ battn) {
    extern __shared__ __half2 dsm[];

    const int tid  = threadIdx.x;
    const int warp = tid >> 5;
    const int lane = tid & 31;
    const int grp  = lane >> 2;
    const int tg   = lane & 3;
    const int m_off = (warp >> 2) * 64;
    const int n_off = (warp & 3) * 32;
    const int bm = blockIdx.y * GBM;
    const int bx = blockIdx.x;

    // operand routing
    const float* Ap; const float* Bp; int Nb, bn;
    if (EPI == 0) { Ap = A;  Bp = B0; Nb = 256; bn = bx * 128; }
    else {
        if (bx < 2)      { Ap = A;  Bp = B0; Nb = 256; bn = bx * 128; }
        else if (bx < 4) { Ap = A2; Bp = B1; Nb = 256; bn = (bx - 2) * 128; }
        else             { Ap = A2; Bp = B2; Nb = 128; bn = 0; }
    }

    float cc[4][4][4];
#pragma unroll
    for (int i = 0; i < 4; i++)
#pragma unroll
        for (int j = 0; j < 4; j++)
#pragma unroll
            for (int r = 0; r < 4; r++) cc[i][j][r] = 0.f;

    // ONE block-uniform branch selecting a fully-specialized mainloop.
    if (EPI == 5 && bx < 2)
        gemm_mainloop<true >(Ap, Bp, Nb, bn, bm, M, K, dsm, cc, tid, grp, tg, m_off, n_off);
    else
        gemm_mainloop<false>(Ap, Bp, Nb, bn, bm, M, K, dsm, cc, tid, grp, tg, m_off, n_off);

    // ======================= epilogues =======================
    if (EPI == 0) {
        float* C = (float*)C0;
#pragma unroll
        for (int am = 0; am < 4; am++) {
            int r0 = bm + m_off + am * 16 + grp;
#pragma unroll
            for (int an = 0; an < 4; an++) {
                int c0 = bn + n_off + an * 8 + 2 * tg;
                if (r0 < M)
                    *(float2*)&C[(size_t)r0 * 256 + c0] = make_float2(cc[am][an][0], cc[am][an][1]);
                if (r0 + 8 < M)
                    *(float2*)&C[(size_t)(r0 + 8) * 256 + c0] = make_float2(cc[am][an][2], cc[am][an][3]);
            }
        }
    } else if (EPI == 5 && bx < 2) {
        // fp16 store -> vproj (N=256, 128 half2 per row)
        __half2* C = (__half2*)C0;
#pragma unroll
        for (int am = 0; am < 4; am++) {
            int r0 = bm + m_off + am * 16 + grp;
#pragma unroll
            for (int an = 0; an < 4; an++) {
                int c0 = bn + n_off + an * 8 + 2 * tg;
                if (r0 < M)
                    C[(size_t)r0 * 128 + (c0 >> 1)] = __floats2half2_rn(cc[am][an][0], cc[am][an][1]);
                if (r0 + 8 < M)
                    C[(size_t)(r0 + 8) * 128 + (c0 >> 1)] = __floats2half2_rn(cc[am][an][2], cc[am][an][3]);
            }
        }
    } else if (EPI == 5 && bx < 4) {
        // sample-info epilogue
        int4* C = (int4*)C1;
#pragma unroll
        for (int am = 0; am < 4; am++) {
#pragma unroll
            for (int rh = 0; rh < 2; rh++) {
                int row = bm + m_off + am * 16 + grp + rh * 8;
                if (row >= M) continue;
#pragma unroll
                for (int an = 0; an < 4; an++) {
                    int c0 = bn + n_off + an * 8 + 2 * tg;   // even: x; c0+1: y
                    int l = (c0 >> 3) & 3;
                    const int Wl = 96 >> l;
                    const int start = 12288 - (12288 >> (2 * l));
                    const float scale = 0.5f * (float)(Wl - 1);
                    float rx = __ldg(&ref[(size_t)row * 8 + l * 2 + 0]);
                    float ry = __ldg(&ref[(size_t)row * 8 + l * 2 + 1]);
                    float o0 = tanhf(cc[am][an][rh * 2 + 0] + __ldg(&boff[c0]));
                    float o1 = tanhf(cc[am][an][rh * 2 + 1] + __ldg(&boff[c0 + 1]));
                    float lx = fminf(fmaxf(rx + o0, -1.f), 1.f);
                    float ly = fminf(fmaxf(ry + o1, -1.f), 1.f);
                    float x = (lx + 1.f) * scale;
                    float y = (ly + 1.f) * scale;
                    float x0f = floorf(x), y0f = floorf(y);
                    float wx = x - x0f, wy = y - y0f;
                    int x0 = min(max((int)x0f, 0), Wl - 1);
                    int x1 = min(x0 + 1, Wl - 1);
                    int y0 = min(max((int)y0f, 0), Wl - 1);
                    int y1 = min(y0 + 1, Wl - 1);
                    int base = (start + y0 * Wl + x0) * 128;
                    int dxdy = (((y1 - y0) * Wl * 128) << 8) | ((x1 - x0) * 128);
                    C[(size_t)row * 128 + (c0 >> 1)] =
                        make_int4(base, dxdy, __float_as_int(wx), __float_as_int(wy));
                }
            }
        }
    } else if (EPI == 5) {
        // softmax epilogue (N=128)
        float* C = (float*)C2;
#pragma unroll
        for (int am = 0; am < 4; am++) {
#pragma unroll
            for (int rh = 0; rh < 2; rh++) {
                int row = bm + m_off + am * 16 + grp + rh * 8;
#pragma unroll
                for (int hd2 = 0; hd2 < 2; hd2++) {
                    float v[4];
#pragma unroll
                    for (int q = 0; q < 4; q++) {
                        int an = hd2 * 2 + (q >> 1);
                        int s = q & 1;
                        int col = n_off + an * 8 + 2 * tg + s;
                        v[q] = cc[am][an][rh * 2 + s] + __ldg(&battn[col]);
                    }
                    float m = fmaxf(fmaxf(v[0], v[1]), fmaxf(v[2], v[3]));
                    m = fmaxf(m, __shfl_xor_sync(0xffffffffu, m, 1));
                    m = fmaxf(m, __shfl_xor_sync(0xffffffffu, m, 2));
                    float e[4], sum = 0.f;
#pragma unroll
                    for (int q = 0; q < 4; q++) { e[q] = __expf(v[q] - m); sum += e[q]; }
                    sum += __shfl_xor_sync(0xffffffffu, sum, 1);
                    sum += __shfl_xor_sync(0xffffffffu, sum, 2);
                    float inv = 1.f / sum;
                    if (row < M) {
#pragma unroll
                        for (int a2 = 0; a2 < 2; a2++) {
                            int an = hd2 * 2 + a2;
                            int c0 = n_off + an * 8 + 2 * tg;
                            *(float2*)&C[(size_t)row * 128 + c0] =
                                make_float2(e[a2 * 2] * inv, e[a2 * 2 + 1] * inv);
                        }
                    }
                }
            }
        }
    }
}

// ---------------------------------------------------------------------------
// Deformable sampling: warp = one (bq, head-quad). 8 lanes per head, each lane
// handles 4 channels via 8B (uint2 = 2x half2) gathers.
// ---------------------------------------------------------------------------
__device__ __forceinline__ float4 ld_corner(const __half2* p) {
    uint2 u = __ldg((const uint2*)p);
    float2 fa = __half22float2(*(__half2*)&u.x);
    float2 fb = __half22float2(*(__half2*)&u.y);
    return make_float4(fa.x, fa.y, fb.x, fb.y);
}

__global__ __launch_bounds__(256)
void sample_half(const __half2* __restrict__ vp,
                 const int4* __restrict__ sinfo,
                 const float* __restrict__ attnw,
                 float* __restrict__ acc) {
    const int gwarp = (blockIdx.x * blockDim.x + threadIdx.x) >> 5;
    const int lane = threadIdx.x & 31;
    if (gwarp >= BQ_ * 2) return;
    const int wp = gwarp & 1;
    const int bq = gwarp >> 1;
    const int b = bq / Q_;
    const int hs = lane >> 3;      // 0..3
    const int c4 = lane & 7;       // channel group (4 channels)
    const int h = wp * 4 + hs;

    const int4*  sp = sinfo + (size_t)bq * 128 + h * 16;
    const float* wq = attnw + (size_t)bq * 128 + h * 16;
    const __half2* vb = vp + (size_t)b * VLEN_ * 128 + h * 16 + c4 * 2;

    float a0 = 0.f, a1 = 0.f, a2 = 0.f, a3 = 0.f;
#pragma unroll
    for (int s = 0; s < 16; s++) {
        int4 si = __ldg(&sp[s]);
        float w = __ldg(&wq[s]);
        float wx = __int_as_float(si.z);
        float wy = __int_as_float(si.w);
        float wb = w * wy;
        float wa = w - wb;
        float w01 = wa * wx, w00 = wa - w01;
        float w11 = wb * wx, w10 = wb - w11;
        int dx = si.y & 255;
        int dy = si.y >> 8;
        const __half2* p = vb + si.x;
        float4 f00 = ld_corner(p);
        float4 f01 = ld_corner(p + dx);
        float4 f10 = ld_corner(p + dy);
        float4 f11 = ld_corner(p + dx + dy);
        a0 = fmaf(w00, f00.x, fmaf(w01, f01.x, fmaf(w10, f10.x, fmaf(w11, f11.x, a0))));
        a1 = fmaf(w00, f00.y, fmaf(w01, f01.y, fmaf(w10, f10.y, fmaf(w11, f11.y, a1))));
        a2 = fmaf(w00, f00.z, fmaf(w01, f01.z, fmaf(w10, f10.z, fmaf(w11, f11.z, a2))));
        a3 = fmaf(w00, f00.w, fmaf(w01, f01.w, fmaf(w10, f10.w, fmaf(w11, f11.w, a3))));
    }
    *(float4*)&acc[(size_t)bq * 256 + h * 32 + c4 * 4] = make_float4(a0, a1, a2, a3);
}

// ---------------------------------------------------------------------------
extern "C" void kernel_launch(void* const* d_in, const int* in_sizes, int n_in,
                              void* d_out, int out_size) {
    const float* queries = (const float*)d_in[0];
    const float* ref     = (const float*)d_in[1];
    const float* value   = (const float*)d_in[2];
    const float* Wv      = (const float*)d_in[3];
    const float* Woff    = (const float*)d_in[4];
    const float* boff    = (const float*)d_in[5];
    const float* Wattn   = (const float*)d_in[6];
    const float* battn   = (const float*)d_in[7];
    const float* Wout    = (const float*)d_in[8];
    float* out = (float*)d_out;

    __half2* vproj;
    int4* sinfo;
    float *attnw, *acc;
    cudaGetSymbolAddress((void**)&vproj, g_vproj_h);
    cudaGetSymbolAddress((void**)&sinfo, g_sinfo);
    cudaGetSymbolAddress((void**)&attnw, g_attnw);
    cudaGetSymbolAddress((void**)&acc,   g_acc);

    cudaFuncSetAttribute(gemm_3xfp16<5>, cudaFuncAttributeMaxDynamicSharedMemorySize, SMEM_TOT);
    cudaFuncSetAttribute(gemm_3xfp16<0>, cudaFuncAttributeMaxDynamicSharedMemorySize, SMEM_TOT);

    const int mblk = (BQ_ + GBM - 1) / GBM;   // 192

    // 1) merged front-end: vproj (1x, specialized) + sinfo + attnw, one launch
    gemm_3xfp16<5><<<dim3(5, mblk), 256, SMEM_TOT>>>(
        value, queries, Wv, Woff, Wattn, vproj, sinfo, attnw,
        BQ_, E_, ref, boff, battn);
    // 2) deformable bilinear sampling
    {
        int total_threads = BQ_ * 2 * 32;
        sample_half<<<(total_threads + 255) / 256, 256>>>(vproj, sinfo, attnw, acc);
    }
    // 3) output projection -> d_out (3x precision)
    gemm_3xfp16<0><<<dim3(2, mblk), 256, SMEM_TOT>>>(
        acc, nullptr, Wout, nullptr, nullptr, out, nullptr, nullptr,
        BQ_, E_, nullptr, nullptr, nullptr);
}